// round 11
// baseline (speedup 1.0000x reference)
#include <cuda_runtime.h>

// Problem shape (fixed by the bench)
#define BB 8
#define SS 2048
#define HH 2048

// Scratch (no allocations allowed)
__device__ float g_uv[BB * SS * 4];      // per-row dots: h·W[:H,0], h·W[:H,1], h·W[H:,0], h·W[H:,1]
__device__ float g_v[BB * SS];           // per-input-position weight in transform
__device__ int   g_seg_start[BB * SS];   // first input s for output row t
__device__ int   g_seg_len[BB * SS];     // number of input s for output row t
__device__ int   g_new_len[BB];

// ---------------------------------------------------------------------------
// Kernel A v4: 512 threads, thread tid owns h columns tid*4..tid*4+3 (16 W
// floats in registers — HALF the register state of v3, so 3 blocks = 48 warps
// = 75% occupancy instead of 24 warps). Tile = 4 rows, 32KB static smem.
// Hot loop: LDG.128 -> 16 FFMA -> STS.128, next-row prefetch, no shuffles.
// ---------------------------------------------------------------------------
__global__ void __launch_bounds__(512, 3) k_dots(const float* __restrict__ h,
                                                 const float* __restrict__ W) {
    const int tid = threadIdx.x;
    const float4* Wp = reinterpret_cast<const float4*>(W);   // W: [2H,2] row-major

    // cols j..j+3 (j = tid*4): first-half W float4s at j/2 = tid*2, +1;
    // second-half at (H+j)/2 = 1024 + tid*2, +1.
    const float4 wa0 = __ldg(Wp + tid * 2 + 0);
    const float4 wa1 = __ldg(Wp + tid * 2 + 1);
    const float4 wb0 = __ldg(Wp + 1024 + tid * 2 + 0);
    const float4 wb1 = __ldg(Wp + 1024 + tid * 2 + 1);

    __shared__ float part[4][512][4];                        // 32KB: [row][tid][comp]

    const int row0 = blockIdx.x * 4;
    const float4* hp = reinterpret_cast<const float4*>(h) + (size_t)row0 * (HH / 4);

    float4 hv = __ldg(hp + tid);

#pragma unroll
    for (int rr = 0; rr < 4; rr++) {
        float4 nv;
        if (rr < 3) nv = __ldg(hp + (rr + 1) * (HH / 4) + tid);   // prefetch next row

        const float a0 = hv.x * wa0.x + hv.y * wa0.z + hv.z * wa1.x + hv.w * wa1.z;
        const float a1 = hv.x * wa0.y + hv.y * wa0.w + hv.z * wa1.y + hv.w * wa1.w;
        const float c0 = hv.x * wb0.x + hv.y * wb0.z + hv.z * wb1.x + hv.w * wb1.z;
        const float c1 = hv.x * wb0.y + hv.y * wb0.w + hv.z * wb1.y + hv.w * wb1.w;

        *reinterpret_cast<float4*>(&part[rr][tid][0]) = make_float4(a0, a1, c0, c1);

        if (rr < 3) hv = nv;
    }
    __syncthreads();                                         // ONE barrier per tile

    // warp w (0..3) reduces row w: lane l sums comp (l&3) over tid ≡ (l>>2) mod 8.
    // float index (g+8k)*4+c has bank (4g+c) == l: conflict-free for all k.
    const int w = tid >> 5, l = tid & 31;
    if (w < 4) {
        const int c = l & 3, g = l >> 2;
        float s = 0.f;
#pragma unroll
        for (int k = 0; k < 64; k++) s += part[w][g + 8 * k][c];
        s += __shfl_down_sync(0xffffffffu, s, 16);
        s += __shfl_down_sync(0xffffffffu, s, 8);
        s += __shfl_down_sync(0xffffffffu, s, 4);
        if (l < 4) g_uv[(size_t)(row0 + w) * 4 + l] = s;
    }
}

// ---------------------------------------------------------------------------
// Kernel B: per-batch. logits, gumbel-softmax, mm, want, v, prefix scan of inc,
// segment map, and all small outputs. One 256-thread block per batch.
// ---------------------------------------------------------------------------
__global__ void __launch_bounds__(256) k_scan(const int* __restrict__ amask,
                                              const int* __restrict__ smask,
                                              const float* __restrict__ gum,
                                              const float* __restrict__ bias,
                                              float* __restrict__ out) {
    const int b = blockIdx.x;
    const int tid = threadIdx.x;
    const size_t base = (size_t)b * SS;

    __shared__ unsigned char want_sh[SS];
    __shared__ int r_sh[SS];
    __shared__ int part[256];
    __shared__ int cnt_sh[SS];
    __shared__ int sst_sh[SS];
    __shared__ int sh_T;

    // output layout: tuple members concatenated, all fp32
    float* out_mask    = out + (size_t)BB * SS * HH;
    float* out_special = out_mask + (size_t)BB * SS;
    float* out_counts  = out_special + (size_t)BB * SS;
    float* out_mm      = out_counts + (size_t)BB * SS;
    float* out_logits  = out_mm + (size_t)BB * SS * 2;

    // --- T = sum(attention_mask[b]) ---
    if (tid == 0) sh_T = 0;
    __syncthreads();
    {
        int local = 0;
#pragma unroll
        for (int i = 0; i < 8; i++) local += amask[base + tid * 8 + i];
        atomicAdd(&sh_T, local);
    }
    __syncthreads();
    const int T = sh_T;

    const float b0v = __ldg(bias + 0), b1v = __ldg(bias + 1);

    // --- per-position: logits, gumbel-softmax, mm, want, v ---
#pragma unroll
    for (int i = 0; i < 8; i++) {
        const int s = tid * 8 + i;
        float l0, l1;
        if (s < SS - 1) {
            const float* uvA = g_uv + (base + s) * 4;
            const float* uvB = g_uv + (base + s + 1) * 4;
            l0 = uvA[0] + uvB[2] + b0v;
            l1 = uvA[1] + uvB[3] + b1v;
        } else {                                     // zero stub row
            l0 = b0v; l1 = b1v;
        }
        out_logits[(base + s) * 2 + 0] = l0;
        out_logits[(base + s) * 2 + 1] = l1;

        const float z0 = l0 + gum[(base + s) * 2 + 0];
        const float z1 = l1 + gum[(base + s) * 2 + 1];
        const float m = fmaxf(z0, z1);
        const float e0 = expf(z0 - m), e1 = expf(z1 - m);
        const float inv = 1.f / (e0 + e1);
        const float ys0 = e0 * inv, ys1 = e1 * inv;
        const int idx1 = (ys1 > ys0) ? 1 : 0;        // argmax, ties -> 0 (matches jnp)
        float mm0 = ((idx1 == 0 ? 1.f : 0.f) - ys0) + ys0;   // straight-through, exact fp order
        float mm1 = ((idx1 == 1 ? 1.f : 0.f) - ys1) + ys1;
        if (smask[base + s]) { mm0 = 1.f; mm1 = 0.f; }
        const float mf = amask[base + s] ? 1.f : 0.f;
        mm0 *= mf; mm1 *= mf;
        out_mm[(base + s) * 2 + 0] = mm0;
        out_mm[(base + s) * 2 + 1] = mm1;

        const bool want = (mm1 > 0.5f) && (s >= 1) && (s < T - 1);
        want_sh[s] = want ? 1 : 0;
        float v = want ? mm1 : mm0;
        if (s == 0) v = 1.f;
        if (s >= T) v = 0.f;
        g_v[base + s] = v;
    }
    __syncthreads();

    // --- inc + block prefix scan -> r ---
    int incs[8];
    {
        int csum = 0;
#pragma unroll
        for (int i = 0; i < 8; i++) {
            const int s = tid * 8 + i;
            const int w = want_sh[s];
            const int wp = (s > 0) ? want_sh[s - 1] : 0;
            const int inc = (s < T && s >= 1 && !(w && wp)) ? 1 : 0;
            csum += inc;
            incs[i] = csum;                          // local inclusive
        }
        part[tid] = csum;
    }
    __syncthreads();
    for (int off = 1; off < 256; off <<= 1) {
        const int add = (tid >= off) ? part[tid - off] : 0;
        __syncthreads();
        part[tid] += add;
        __syncthreads();
    }
    {
        const int offset = (tid > 0) ? part[tid - 1] : 0;
#pragma unroll
        for (int i = 0; i < 8; i++) r_sh[tid * 8 + i] = offset + incs[i];
    }
    __syncthreads();

    // --- segment map via shared atomics ---
#pragma unroll
    for (int i = 0; i < 8; i++) { cnt_sh[tid * 8 + i] = 0; sst_sh[tid * 8 + i] = 0x7fffffff; }
    __syncthreads();
#pragma unroll
    for (int i = 0; i < 8; i++) {
        const int s = tid * 8 + i;
        if (s < T) {
            const int r = r_sh[s];
            atomicAdd(&cnt_sh[r], 1);
            atomicMin(&sst_sh[r], s);
        }
    }
    __syncthreads();

    const int nl = r_sh[SS - 1] + 1;                 // matches reference r[:, -1] + 1
#pragma unroll
    for (int i = 0; i < 8; i++) {
        const int t = tid * 8 + i;
        out_mask[base + t]    = (t < nl) ? 1.f : 0.f;
        out_special[base + t] = (t == 0 || t == nl - 1) ? 1.f : 0.f;
        out_counts[base + t]  = (float)cnt_sh[t];
        g_seg_start[base + t] = sst_sh[t];
        g_seg_len[base + t]   = cnt_sh[t];
    }
    if (tid == 0) g_new_len[b] = nl;
}

// ---------------------------------------------------------------------------
// Kernel C: 8 output rows per 256-thread block. Consecutive output rows own
// contiguous input runs, so each block streams a contiguous ~10-row span of h.
// Blocks traverse rows DESCENDING (L2 reuse of k_dots' ascending stream);
// output stores are __stcs (evict-first) to protect the h working set.
// ---------------------------------------------------------------------------
__global__ void __launch_bounds__(256) k_merge(const float* __restrict__ h,
                                               float* __restrict__ out) {
    const int blk = (BB * SS / 8 - 1) - blockIdx.x;  // descending traversal
    const int t0 = blk * 8;                          // first global output row
    const int b = t0 >> 11;                          // batch (8 rows never straddle)
    const int tid = threadIdx.x;
    const int q0 = tid * 2;
    const int nl = g_new_len[b];
    const size_t base = (size_t)b * SS;

#pragma unroll
    for (int j = 0; j < 8; j++) {
        const int row = t0 + j;                      // global output row index
        const int t = row & (SS - 1);
        float4 acc0 = make_float4(0.f, 0.f, 0.f, 0.f);
        float4 acc1 = make_float4(0.f, 0.f, 0.f, 0.f);

        if (t < nl) {
            const int s0 = g_seg_start[row];
            const int L  = g_seg_len[row];
            for (int i = 0; i < L; i++) {
                const size_t srow = base + s0 + i;
                const float w = __ldg(g_v + srow);
                const float4* hr = reinterpret_cast<const float4*>(h) + srow * (HH / 4);
                const float4 x0 = __ldg(hr + q0);
                const float4 x1 = __ldg(hr + q0 + 1);
                acc0.x += w * x0.x; acc0.y += w * x0.y; acc0.z += w * x0.z; acc0.w += w * x0.w;
                acc1.x += w * x1.x; acc1.y += w * x1.y; acc1.z += w * x1.z; acc1.w += w * x1.w;
            }
        }
        float4* orow = reinterpret_cast<float4*>(out) + (size_t)row * (HH / 4);
        __stcs(orow + q0,     acc0);
        __stcs(orow + q0 + 1, acc1);
    }
}

// ---------------------------------------------------------------------------
extern "C" void kernel_launch(void* const* d_in, const int* in_sizes, int n_in,
                              void* d_out, int out_size) {
    const float* h     = (const float*)d_in[0];   // [B,S,H] f32
    const int*   amask = (const int*)d_in[1];     // [B,S]   i32
    const int*   smask = (const int*)d_in[2];     // [B,S]   i32
    const float* gum   = (const float*)d_in[3];   // [B,S,2] f32
    const float* W     = (const float*)d_in[4];   // [2H,2]  f32
    const float* bias  = (const float*)d_in[5];   // [2]     f32
    float* out = (float*)d_out;

    k_dots<<<(BB * SS) / 4, 512>>>(h, W);
    k_scan<<<BB, 256>>>(amask, smask, gum, bias, out);
    k_merge<<<(BB * SS) / 8, 256>>>(h, out);
}

// round 12
// speedup vs baseline: 1.0369x; 1.0369x over previous
#include <cuda_runtime.h>

// Problem shape (fixed by the bench)
#define BB 8
#define SS 2048
#define HH 2048

// Scratch (no allocations allowed)
__device__ __align__(16) float g_uv[BB * SS * 4];  // per-row dots
__device__ float g_v[BB * SS];           // per-input-position weight in transform
__device__ unsigned char g_want[BB * SS];
__device__ int   g_T[BB];
__device__ int   g_seg_start[BB * SS];   // first input s for output row t
__device__ int   g_seg_len[BB * SS];     // number of input s for output row t
__device__ int   g_new_len[BB];

// ---------------------------------------------------------------------------
// Kernel T: per-batch valid-token counts. One block; warp w reduces batch w.
// ---------------------------------------------------------------------------
__global__ void __launch_bounds__(256) k_T(const int* __restrict__ amask) {
    const int w = threadIdx.x >> 5, l = threadIdx.x & 31;
    int s = 0;
    for (int i = l; i < SS; i += 32) s += amask[w * SS + i];
#pragma unroll
    for (int off = 16; off > 0; off >>= 1) s += __shfl_down_sync(0xffffffffu, s, off);
    if (l == 0) g_T[w] = s;
}

// ---------------------------------------------------------------------------
// Kernel A v5: thread tid owns h columns tid*4..tid*4+3 (16 W floats in regs).
// All 4 row-loads of the tile are issued UPFRONT (MLP=4 per thread), then
// FFMA + STS.128 per row; one barrier; LDS.128 tail reduce (once per tile).
// ---------------------------------------------------------------------------
__global__ void __launch_bounds__(512, 2) k_dots(const float* __restrict__ h,
                                                 const float* __restrict__ W) {
    const int tid = threadIdx.x;
    const float4* Wp = reinterpret_cast<const float4*>(W);   // W: [2H,2] row-major

    const float4 wa0 = __ldg(Wp + tid * 2 + 0);
    const float4 wa1 = __ldg(Wp + tid * 2 + 1);
    const float4 wb0 = __ldg(Wp + 1024 + tid * 2 + 0);
    const float4 wb1 = __ldg(Wp + 1024 + tid * 2 + 1);

    __shared__ float part[4][512][4];                        // 32KB

    const int row0 = blockIdx.x * 4;
    const float4* hp = reinterpret_cast<const float4*>(h) + (size_t)row0 * (HH / 4);

    // 4 independent loads in flight before any consumer
    float4 hv[4];
    hv[0] = __ldg(hp + tid);
    hv[1] = __ldg(hp + 512 + tid);
    hv[2] = __ldg(hp + 1024 + tid);
    hv[3] = __ldg(hp + 1536 + tid);

#pragma unroll
    for (int rr = 0; rr < 4; rr++) {
        const float4 x = hv[rr];
        const float a0 = x.x * wa0.x + x.y * wa0.z + x.z * wa1.x + x.w * wa1.z;
        const float a1 = x.x * wa0.y + x.y * wa0.w + x.z * wa1.y + x.w * wa1.w;
        const float c0 = x.x * wb0.x + x.y * wb0.z + x.z * wb1.x + x.w * wb1.z;
        const float c1 = x.x * wb0.y + x.y * wb0.w + x.z * wb1.y + x.w * wb1.w;
        *reinterpret_cast<float4*>(&part[rr][tid][0]) = make_float4(a0, a1, c0, c1);
    }
    __syncthreads();                                         // ONE barrier per tile

    // warp w (0..3) reduces row w with LDS.128: lane l accumulates a float4
    // over tids l, l+32, ..., l+480 (16 iterations), then 5-level shuffle.
    const int w = tid >> 5, l = tid & 31;
    if (w < 4) {
        float4 acc = make_float4(0.f, 0.f, 0.f, 0.f);
#pragma unroll
        for (int k = 0; k < 16; k++) {
            const float4 p = *reinterpret_cast<const float4*>(&part[w][l + 32 * k][0]);
            acc.x += p.x; acc.y += p.y; acc.z += p.z; acc.w += p.w;
        }
#pragma unroll
        for (int off = 16; off > 0; off >>= 1) {
            acc.x += __shfl_down_sync(0xffffffffu, acc.x, off);
            acc.y += __shfl_down_sync(0xffffffffu, acc.y, off);
            acc.z += __shfl_down_sync(0xffffffffu, acc.z, off);
            acc.w += __shfl_down_sync(0xffffffffu, acc.w, off);
        }
        if (l == 0)
            *reinterpret_cast<float4*>(&g_uv[(size_t)(row0 + w) * 4]) = acc;
    }
}

// ---------------------------------------------------------------------------
// Kernel P: per-position work, chip-wide parallel (was the hot half of the
// old 8-block k_scan). One thread per position: logits, gumbel-softmax, mm,
// want, v; writes out_logits/out_mm/g_v/g_want.
// ---------------------------------------------------------------------------
__global__ void __launch_bounds__(256) k_point(const int* __restrict__ amask,
                                               const int* __restrict__ smask,
                                               const float* __restrict__ gum,
                                               const float* __restrict__ bias,
                                               float* __restrict__ out) {
    const int sg = blockIdx.x * 256 + threadIdx.x;           // 0..BB*SS-1
    const int s = sg & (SS - 1);
    const int b = sg >> 11;
    const int T = g_T[b];

    float* out_mm     = out + (size_t)BB * SS * HH + (size_t)3 * BB * SS;
    float* out_logits = out_mm + (size_t)BB * SS * 2;

    const float b0v = __ldg(bias + 0), b1v = __ldg(bias + 1);

    float l0, l1;
    if (s < SS - 1) {
        const float4 uvA = *reinterpret_cast<const float4*>(&g_uv[(size_t)sg * 4]);
        const float4 uvB = *reinterpret_cast<const float4*>(&g_uv[(size_t)(sg + 1) * 4]);
        l0 = uvA.x + uvB.z + b0v;
        l1 = uvA.y + uvB.w + b1v;
    } else {                                                 // zero stub row
        l0 = b0v; l1 = b1v;
    }
    out_logits[(size_t)sg * 2 + 0] = l0;
    out_logits[(size_t)sg * 2 + 1] = l1;

    const float z0 = l0 + gum[(size_t)sg * 2 + 0];
    const float z1 = l1 + gum[(size_t)sg * 2 + 1];
    const float m = fmaxf(z0, z1);
    const float e0 = expf(z0 - m), e1 = expf(z1 - m);
    const float inv = 1.f / (e0 + e1);
    const float ys0 = e0 * inv, ys1 = e1 * inv;
    const int idx1 = (ys1 > ys0) ? 1 : 0;                    // argmax, ties -> 0
    float mm0 = ((idx1 == 0 ? 1.f : 0.f) - ys0) + ys0;       // straight-through, exact fp order
    float mm1 = ((idx1 == 1 ? 1.f : 0.f) - ys1) + ys1;
    if (smask[sg]) { mm0 = 1.f; mm1 = 0.f; }
    const float mf = amask[sg] ? 1.f : 0.f;
    mm0 *= mf; mm1 *= mf;
    out_mm[(size_t)sg * 2 + 0] = mm0;
    out_mm[(size_t)sg * 2 + 1] = mm1;

    const bool want = (mm1 > 0.5f) && (s >= 1) && (s < T - 1);
    g_want[sg] = want ? 1 : 0;
    float v = want ? mm1 : mm0;
    if (s == 0) v = 1.f;
    if (s >= T) v = 0.f;
    g_v[sg] = v;
}

// ---------------------------------------------------------------------------
// Kernel B2: the irreducibly-serial per-batch part: prefix scan of inc over
// want, segment map, small outputs. Pure smem work, no expf, no gathers.
// ---------------------------------------------------------------------------
__global__ void __launch_bounds__(256) k_scan2(float* __restrict__ out) {
    const int b = blockIdx.x;
    const int tid = threadIdx.x;
    const size_t base = (size_t)b * SS;

    __shared__ unsigned char want_sh[SS];
    __shared__ int r_sh[SS];
    __shared__ int part[256];
    __shared__ int cnt_sh[SS];
    __shared__ int sst_sh[SS];

    float* out_mask    = out + (size_t)BB * SS * HH;
    float* out_special = out_mask + (size_t)BB * SS;
    float* out_counts  = out_special + (size_t)BB * SS;

    const int T = g_T[b];

    // load want bytes (8 per thread via one 64-bit load)
    {
        const unsigned long long w8 =
            *reinterpret_cast<const unsigned long long*>(g_want + base + tid * 8);
#pragma unroll
        for (int i = 0; i < 8; i++)
            want_sh[tid * 8 + i] = (unsigned char)((w8 >> (8 * i)) & 0xff);
    }
    __syncthreads();

    // --- inc + block prefix scan -> r ---
    int incs[8];
    {
        int csum = 0;
#pragma unroll
        for (int i = 0; i < 8; i++) {
            const int s = tid * 8 + i;
            const int w = want_sh[s];
            const int wp = (s > 0) ? want_sh[s - 1] : 0;
            const int inc = (s < T && s >= 1 && !(w && wp)) ? 1 : 0;
            csum += inc;
            incs[i] = csum;                          // local inclusive
        }
        part[tid] = csum;
    }
    __syncthreads();
    for (int off = 1; off < 256; off <<= 1) {
        const int add = (tid >= off) ? part[tid - off] : 0;
        __syncthreads();
        part[tid] += add;
        __syncthreads();
    }
    {
        const int offset = (tid > 0) ? part[tid - 1] : 0;
#pragma unroll
        for (int i = 0; i < 8; i++) r_sh[tid * 8 + i] = offset + incs[i];
    }
    __syncthreads();

    // --- segment map via shared atomics ---
#pragma unroll
    for (int i = 0; i < 8; i++) { cnt_sh[tid * 8 + i] = 0; sst_sh[tid * 8 + i] = 0x7fffffff; }
    __syncthreads();
#pragma unroll
    for (int i = 0; i < 8; i++) {
        const int s = tid * 8 + i;
        if (s < T) {
            const int r = r_sh[s];
            atomicAdd(&cnt_sh[r], 1);
            atomicMin(&sst_sh[r], s);
        }
    }
    __syncthreads();

    const int nl = r_sh[SS - 1] + 1;                 // matches reference r[:, -1] + 1
#pragma unroll
    for (int i = 0; i < 8; i++) {
        const int t = tid * 8 + i;
        out_mask[base + t]    = (t < nl) ? 1.f : 0.f;
        out_special[base + t] = (t == 0 || t == nl - 1) ? 1.f : 0.f;
        out_counts[base + t]  = (float)cnt_sh[t];
        g_seg_start[base + t] = sst_sh[t];
        g_seg_len[base + t]   = cnt_sh[t];
    }
    if (tid == 0) g_new_len[b] = nl;
}

// ---------------------------------------------------------------------------
// Kernel C: 8 output rows per 256-thread block. Consecutive output rows own
// contiguous input runs, so each block streams a contiguous ~10-row span of h.
// Blocks traverse rows DESCENDING (L2 reuse of k_dots' ascending stream);
// output stores are __stcs (evict-first) to protect the h working set.
// ---------------------------------------------------------------------------
__global__ void __launch_bounds__(256) k_merge(const float* __restrict__ h,
                                               float* __restrict__ out) {
    const int blk = (BB * SS / 8 - 1) - blockIdx.x;  // descending traversal
    const int t0 = blk * 8;                          // first global output row
    const int b = t0 >> 11;                          // batch (8 rows never straddle)
    const int tid = threadIdx.x;
    const int q0 = tid * 2;
    const int nl = g_new_len[b];
    const size_t base = (size_t)b * SS;

#pragma unroll
    for (int j = 0; j < 8; j++) {
        const int row = t0 + j;                      // global output row index
        const int t = row & (SS - 1);
        float4 acc0 = make_float4(0.f, 0.f, 0.f, 0.f);
        float4 acc1 = make_float4(0.f, 0.f, 0.f, 0.f);

        if (t < nl) {
            const int s0 = g_seg_start[row];
            const int L  = g_seg_len[row];
            for (int i = 0; i < L; i++) {
                const size_t srow = base + s0 + i;
                const float w = __ldg(g_v + srow);
                const float4* hr = reinterpret_cast<const float4*>(h) + srow * (HH / 4);
                const float4 x0 = __ldg(hr + q0);
                const float4 x1 = __ldg(hr + q0 + 1);
                acc0.x += w * x0.x; acc0.y += w * x0.y; acc0.z += w * x0.z; acc0.w += w * x0.w;
                acc1.x += w * x1.x; acc1.y += w * x1.y; acc1.z += w * x1.z; acc1.w += w * x1.w;
            }
        }
        float4* orow = reinterpret_cast<float4*>(out) + (size_t)row * (HH / 4);
        __stcs(orow + q0,     acc0);
        __stcs(orow + q0 + 1, acc1);
    }
}

// ---------------------------------------------------------------------------
extern "C" void kernel_launch(void* const* d_in, const int* in_sizes, int n_in,
                              void* d_out, int out_size) {
    const float* h     = (const float*)d_in[0];   // [B,S,H] f32
    const int*   amask = (const int*)d_in[1];     // [B,S]   i32
    const int*   smask = (const int*)d_in[2];     // [B,S]   i32
    const float* gum   = (const float*)d_in[3];   // [B,S,2] f32
    const float* W     = (const float*)d_in[4];   // [2H,2]  f32
    const float* bias  = (const float*)d_in[5];   // [2]     f32
    float* out = (float*)d_out;

    k_T<<<1, 256>>>(amask);
    k_dots<<<(BB * SS) / 4, 512>>>(h, W);
    k_point<<<(BB * SS) / 256, 256>>>(amask, smask, gum, bias, out);
    k_scan2<<<BB, 256>>>(out);
    k_merge<<<(BB * SS) / 8, 256>>>(h, out);
}

// round 13
// speedup vs baseline: 1.0664x; 1.0284x over previous
#include <cuda_runtime.h>

// Problem shape (fixed by the bench)
#define BB 8
#define SS 2048
#define HH 2048

// Scratch (no allocations allowed)
__device__ __align__(16) float g_uv[BB * SS * 4];  // per-row dots
__device__ float g_v[BB * SS];           // per-input-position weight in transform
__device__ int   g_seg_start[BB * SS];   // first input s for output row t
__device__ int   g_seg_len[BB * SS];     // number of input s for output row t
__device__ int   g_new_len[BB];

// ---------------------------------------------------------------------------
// Kernel A v5: thread tid owns h columns tid*4..tid*4+3 (16 W floats in regs).
// All 4 row-loads of the tile are issued UPFRONT (MLP=4 per thread), then
// FFMA + STS.128 per row; one barrier; LDS.128 tail reduce (once per tile).
// ---------------------------------------------------------------------------
__global__ void __launch_bounds__(512, 2) k_dots(const float* __restrict__ h,
                                                 const float* __restrict__ W) {
    const int tid = threadIdx.x;
    const float4* Wp = reinterpret_cast<const float4*>(W);   // W: [2H,2] row-major

    const float4 wa0 = __ldg(Wp + tid * 2 + 0);
    const float4 wa1 = __ldg(Wp + tid * 2 + 1);
    const float4 wb0 = __ldg(Wp + 1024 + tid * 2 + 0);
    const float4 wb1 = __ldg(Wp + 1024 + tid * 2 + 1);

    __shared__ float part[4][512][4];                        // 32KB

    const int row0 = blockIdx.x * 4;
    const float4* hp = reinterpret_cast<const float4*>(h) + (size_t)row0 * (HH / 4);

    // 4 independent loads in flight before any consumer
    float4 hv[4];
    hv[0] = __ldg(hp + tid);
    hv[1] = __ldg(hp + 512 + tid);
    hv[2] = __ldg(hp + 1024 + tid);
    hv[3] = __ldg(hp + 1536 + tid);

#pragma unroll
    for (int rr = 0; rr < 4; rr++) {
        const float4 x = hv[rr];
        const float a0 = x.x * wa0.x + x.y * wa0.z + x.z * wa1.x + x.w * wa1.z;
        const float a1 = x.x * wa0.y + x.y * wa0.w + x.z * wa1.y + x.w * wa1.w;
        const float c0 = x.x * wb0.x + x.y * wb0.z + x.z * wb1.x + x.w * wb1.z;
        const float c1 = x.x * wb0.y + x.y * wb0.w + x.z * wb1.y + x.w * wb1.w;
        *reinterpret_cast<float4*>(&part[rr][tid][0]) = make_float4(a0, a1, c0, c1);
    }
    __syncthreads();                                         // ONE barrier per tile

    // warp w (0..3) reduces row w with LDS.128 + 5-level shuffle.
    const int w = tid >> 5, l = tid & 31;
    if (w < 4) {
        float4 acc = make_float4(0.f, 0.f, 0.f, 0.f);
#pragma unroll
        for (int k = 0; k < 16; k++) {
            const float4 p = *reinterpret_cast<const float4*>(&part[w][l + 32 * k][0]);
            acc.x += p.x; acc.y += p.y; acc.z += p.z; acc.w += p.w;
        }
#pragma unroll
        for (int off = 16; off > 0; off >>= 1) {
            acc.x += __shfl_down_sync(0xffffffffu, acc.x, off);
            acc.y += __shfl_down_sync(0xffffffffu, acc.y, off);
            acc.z += __shfl_down_sync(0xffffffffu, acc.z, off);
            acc.w += __shfl_down_sync(0xffffffffu, acc.w, off);
        }
        if (l == 0)
            *reinterpret_cast<float4*>(&g_uv[(size_t)(row0 + w) * 4]) = acc;
    }
}

// ---------------------------------------------------------------------------
// Kernel P: per-position work, chip-wide parallel: logits, gumbel-softmax, mm.
// (want/v/T handling moved into k_scan2 so this has NO dependency on T.)
// ---------------------------------------------------------------------------
__global__ void __launch_bounds__(256) k_point(const int* __restrict__ amask,
                                               const int* __restrict__ smask,
                                               const float* __restrict__ gum,
                                               const float* __restrict__ bias,
                                               float* __restrict__ out) {
    const int sg = blockIdx.x * 256 + threadIdx.x;           // 0..BB*SS-1
    const int s = sg & (SS - 1);

    float* out_mm     = out + (size_t)BB * SS * HH + (size_t)3 * BB * SS;
    float* out_logits = out_mm + (size_t)BB * SS * 2;

    const float b0v = __ldg(bias + 0), b1v = __ldg(bias + 1);

    float l0, l1;
    if (s < SS - 1) {
        const float4 uvA = *reinterpret_cast<const float4*>(&g_uv[(size_t)sg * 4]);
        const float4 uvB = *reinterpret_cast<const float4*>(&g_uv[(size_t)(sg + 1) * 4]);
        l0 = uvA.x + uvB.z + b0v;
        l1 = uvA.y + uvB.w + b1v;
    } else {                                                 // zero stub row
        l0 = b0v; l1 = b1v;
    }
    out_logits[(size_t)sg * 2 + 0] = l0;
    out_logits[(size_t)sg * 2 + 1] = l1;

    const float z0 = l0 + gum[(size_t)sg * 2 + 0];
    const float z1 = l1 + gum[(size_t)sg * 2 + 1];
    const float m = fmaxf(z0, z1);
    const float e0 = expf(z0 - m), e1 = expf(z1 - m);
    const float inv = 1.f / (e0 + e1);
    const float ys0 = e0 * inv, ys1 = e1 * inv;
    const int idx1 = (ys1 > ys0) ? 1 : 0;                    // argmax, ties -> 0
    float mm0 = ((idx1 == 0 ? 1.f : 0.f) - ys0) + ys0;       // straight-through, exact fp order
    float mm1 = ((idx1 == 1 ? 1.f : 0.f) - ys1) + ys1;
    if (smask[sg]) { mm0 = 1.f; mm1 = 0.f; }
    const float mf = amask[sg] ? 1.f : 0.f;
    mm0 *= mf; mm1 *= mf;
    out_mm[(size_t)sg * 2 + 0] = mm0;
    out_mm[(size_t)sg * 2 + 1] = mm1;
}

// ---------------------------------------------------------------------------
// Kernel B3: per-batch serial part, minimal barriers. Computes T, want, v,
// the prefix scan of inc (warp-0 shuffle scan), segment map, small outputs.
// ---------------------------------------------------------------------------
__global__ void __launch_bounds__(256) k_scan2(const int* __restrict__ amask,
                                               float* __restrict__ out) {
    const int b = blockIdx.x;
    const int tid = threadIdx.x;
    const size_t base = (size_t)b * SS;

    __shared__ unsigned char want_sh[SS];
    __shared__ int r_sh[SS];
    __shared__ int part[256];
    __shared__ int cnt_sh[SS];
    __shared__ int sst_sh[SS];
    __shared__ int sh_T;

    float* out_mask    = out + (size_t)BB * SS * HH;
    float* out_special = out_mask + (size_t)BB * SS;
    float* out_counts  = out_special + (size_t)BB * SS;
    const float* out_mm = out_counts + (size_t)BB * SS;

    // --- T: thread partials + warp-0 reduce (2 barriers) ---
    {
        int local = 0;
#pragma unroll
        for (int i = 0; i < 8; i++) local += amask[base + tid * 8 + i];
        part[tid] = local;
    }
    __syncthreads();
    if (tid < 32) {
        int s = 0;
#pragma unroll
        for (int i = 0; i < 8; i++) s += part[tid * 8 + i];
#pragma unroll
        for (int off = 16; off > 0; off >>= 1) s += __shfl_down_sync(0xffffffffu, s, off);
        if (tid == 0) sh_T = s;
    }
    __syncthreads();
    const int T = sh_T;

    // --- want + v from out_mm (4 float4 loads per thread) ---
#pragma unroll
    for (int q = 0; q < 4; q++) {
        const float4 mm2 = *reinterpret_cast<const float4*>(
            out_mm + (base + tid * 8) * 2 + q * 4);          // positions tid*8+2q, +1
        const int s0 = tid * 8 + q * 2;
        // position s0: mm0=mm2.x, mm1=mm2.y ; position s0+1: mm0=mm2.z, mm1=mm2.w
        const bool w0 = (mm2.y > 0.5f) && (s0 >= 1) && (s0 < T - 1);
        const bool w1 = (mm2.w > 0.5f) && (s0 + 1 >= 1) && (s0 + 1 < T - 1);
        want_sh[s0]     = w0 ? 1 : 0;
        want_sh[s0 + 1] = w1 ? 1 : 0;
        float v0 = w0 ? mm2.y : mm2.x;
        float v1 = w1 ? mm2.w : mm2.z;
        if (s0 == 0) v0 = 1.f;
        if (s0 >= T) v0 = 0.f;
        if (s0 + 1 >= T) v1 = 0.f;
        g_v[base + s0]     = v0;
        g_v[base + s0 + 1] = v1;
    }
    __syncthreads();

    // --- inc + scan: thread partials, warp-0 shuffle scan (2 barriers) ---
    int incs[8];
    {
        int csum = 0;
#pragma unroll
        for (int i = 0; i < 8; i++) {
            const int s = tid * 8 + i;
            const int w = want_sh[s];
            const int wp = (s > 0) ? want_sh[s - 1] : 0;
            const int inc = (s < T && s >= 1 && !(w && wp)) ? 1 : 0;
            csum += inc;
            incs[i] = csum;                          // local inclusive
        }
        part[tid] = csum;
    }
    __syncthreads();
    if (tid < 32) {
        int vals[8];
        int tot = 0;
#pragma unroll
        for (int i = 0; i < 8; i++) { tot += part[tid * 8 + i]; vals[i] = tot; }
        int sc = tot;
#pragma unroll
        for (int off = 1; off < 32; off <<= 1) {
            const int n = __shfl_up_sync(0xffffffffu, sc, off);
            if (tid >= off) sc += n;
        }
        const int excl = sc - tot;
#pragma unroll
        for (int i = 0; i < 8; i++) part[tid * 8 + i] = excl + vals[i];
    }
    __syncthreads();
    {
        const int offset = (tid > 0) ? part[tid - 1] : 0;
#pragma unroll
        for (int i = 0; i < 8; i++) r_sh[tid * 8 + i] = offset + incs[i];
    }

    // --- segment map via shared atomics ---
#pragma unroll
    for (int i = 0; i < 8; i++) { cnt_sh[tid * 8 + i] = 0; sst_sh[tid * 8 + i] = 0x7fffffff; }
    __syncthreads();
#pragma unroll
    for (int i = 0; i < 8; i++) {
        const int s = tid * 8 + i;
        if (s < T) {
            const int r = r_sh[s];
            atomicAdd(&cnt_sh[r], 1);
            atomicMin(&sst_sh[r], s);
        }
    }
    __syncthreads();

    const int nl = r_sh[SS - 1] + 1;                 // matches reference r[:, -1] + 1
#pragma unroll
    for (int i = 0; i < 8; i++) {
        const int t = tid * 8 + i;
        out_mask[base + t]    = (t < nl) ? 1.f : 0.f;
        out_special[base + t] = (t == 0 || t == nl - 1) ? 1.f : 0.f;
        out_counts[base + t]  = (float)cnt_sh[t];
        g_seg_start[base + t] = sst_sh[t];
        g_seg_len[base + t]   = cnt_sh[t];
    }
    if (tid == 0) g_new_len[b] = nl;
}

// ---------------------------------------------------------------------------
// Kernel C: 8 output rows per 256-thread block. Consecutive output rows own
// contiguous input runs, so each block streams a contiguous ~10-row span of h.
// Blocks traverse rows DESCENDING (L2 reuse of k_dots' ascending stream);
// output stores are __stcs (evict-first) to protect the h working set.
// ---------------------------------------------------------------------------
__global__ void __launch_bounds__(256) k_merge(const float* __restrict__ h,
                                               float* __restrict__ out) {
    const int blk = (BB * SS / 8 - 1) - blockIdx.x;  // descending traversal
    const int t0 = blk * 8;                          // first global output row
    const int b = t0 >> 11;                          // batch (8 rows never straddle)
    const int tid = threadIdx.x;
    const int q0 = tid * 2;
    const int nl = g_new_len[b];
    const size_t base = (size_t)b * SS;

#pragma unroll
    for (int j = 0; j < 8; j++) {
        const int row = t0 + j;                      // global output row index
        const int t = row & (SS - 1);
        float4 acc0 = make_float4(0.f, 0.f, 0.f, 0.f);
        float4 acc1 = make_float4(0.f, 0.f, 0.f, 0.f);

        if (t < nl) {
            const int s0 = g_seg_start[row];
            const int L  = g_seg_len[row];
            for (int i = 0; i < L; i++) {
                const size_t srow = base + s0 + i;
                const float w = __ldg(g_v + srow);
                const float4* hr = reinterpret_cast<const float4*>(h) + srow * (HH / 4);
                const float4 x0 = __ldg(hr + q0);
                const float4 x1 = __ldg(hr + q0 + 1);
                acc0.x += w * x0.x; acc0.y += w * x0.y; acc0.z += w * x0.z; acc0.w += w * x0.w;
                acc1.x += w * x1.x; acc1.y += w * x1.y; acc1.z += w * x1.z; acc1.w += w * x1.w;
            }
        }
        float4* orow = reinterpret_cast<float4*>(out) + (size_t)row * (HH / 4);
        __stcs(orow + q0,     acc0);
        __stcs(orow + q0 + 1, acc1);
    }
}

// ---------------------------------------------------------------------------
extern "C" void kernel_launch(void* const* d_in, const int* in_sizes, int n_in,
                              void* d_out, int out_size) {
    const float* h     = (const float*)d_in[0];   // [B,S,H] f32
    const int*   amask = (const int*)d_in[1];     // [B,S]   i32
    const int*   smask = (const int*)d_in[2];     // [B,S]   i32
    const float* gum   = (const float*)d_in[3];   // [B,S,2] f32
    const float* W     = (const float*)d_in[4];   // [2H,2]  f32
    const float* bias  = (const float*)d_in[5];   // [2]     f32
    float* out = (float*)d_out;

    k_dots<<<(BB * SS) / 4, 512>>>(h, W);
    k_point<<<(BB * SS) / 256, 256>>>(amask, smask, gum, bias, out);
    k_scan2<<<BB, 256>>>(amask, out);
    k_merge<<<(BB * SS) / 8, 256>>>(h, out);
}

// round 14
// speedup vs baseline: 1.0818x; 1.0144x over previous
#include <cuda_runtime.h>

// Problem shape (fixed by the bench)
#define BB 8
#define SS 2048
#define HH 2048

// Scratch (no allocations allowed)
__device__ __align__(16) float g_uv[BB * SS * 4];  // per-row dots
__device__ __align__(16) float g_v[BB * SS];       // per-input-position weight
__device__ __align__(16) int   g_seg_start[BB * SS];  // first input s for output row t
__device__ __align__(16) int   g_seg_len[BB * SS];    // inputs per output row t (0 for t>=new_len)
__device__ int   g_new_len[BB];

// ---------------------------------------------------------------------------
// Kernel A v5: thread tid owns h columns tid*4..tid*4+3 (16 W floats in regs).
// All 4 row-loads of the tile are issued UPFRONT (MLP=4 per thread), then
// FFMA + STS.128 per row; one barrier; LDS.128 tail reduce (once per tile).
// ---------------------------------------------------------------------------
__global__ void __launch_bounds__(512, 2) k_dots(const float* __restrict__ h,
                                                 const float* __restrict__ W) {
    const int tid = threadIdx.x;
    const float4* Wp = reinterpret_cast<const float4*>(W);   // W: [2H,2] row-major

    const float4 wa0 = __ldg(Wp + tid * 2 + 0);
    const float4 wa1 = __ldg(Wp + tid * 2 + 1);
    const float4 wb0 = __ldg(Wp + 1024 + tid * 2 + 0);
    const float4 wb1 = __ldg(Wp + 1024 + tid * 2 + 1);

    __shared__ float part[4][512][4];                        // 32KB

    const int row0 = blockIdx.x * 4;
    const float4* hp = reinterpret_cast<const float4*>(h) + (size_t)row0 * (HH / 4);

    // 4 independent loads in flight before any consumer
    float4 hv[4];
    hv[0] = __ldg(hp + tid);
    hv[1] = __ldg(hp + 512 + tid);
    hv[2] = __ldg(hp + 1024 + tid);
    hv[3] = __ldg(hp + 1536 + tid);

#pragma unroll
    for (int rr = 0; rr < 4; rr++) {
        const float4 x = hv[rr];
        const float a0 = x.x * wa0.x + x.y * wa0.z + x.z * wa1.x + x.w * wa1.z;
        const float a1 = x.x * wa0.y + x.y * wa0.w + x.z * wa1.y + x.w * wa1.w;
        const float c0 = x.x * wb0.x + x.y * wb0.z + x.z * wb1.x + x.w * wb1.z;
        const float c1 = x.x * wb0.y + x.y * wb0.w + x.z * wb1.y + x.w * wb1.w;
        *reinterpret_cast<float4*>(&part[rr][tid][0]) = make_float4(a0, a1, c0, c1);
    }
    __syncthreads();                                         // ONE barrier per tile

    // warp w (0..3) reduces row w with LDS.128 + 5-level shuffle.
    const int w = tid >> 5, l = tid & 31;
    if (w < 4) {
        float4 acc = make_float4(0.f, 0.f, 0.f, 0.f);
#pragma unroll
        for (int k = 0; k < 16; k++) {
            const float4 p = *reinterpret_cast<const float4*>(&part[w][l + 32 * k][0]);
            acc.x += p.x; acc.y += p.y; acc.z += p.z; acc.w += p.w;
        }
#pragma unroll
        for (int off = 16; off > 0; off >>= 1) {
            acc.x += __shfl_down_sync(0xffffffffu, acc.x, off);
            acc.y += __shfl_down_sync(0xffffffffu, acc.y, off);
            acc.z += __shfl_down_sync(0xffffffffu, acc.z, off);
            acc.w += __shfl_down_sync(0xffffffffu, acc.w, off);
        }
        if (l == 0)
            *reinterpret_cast<float4*>(&g_uv[(size_t)(row0 + w) * 4]) = acc;
    }
}

// ---------------------------------------------------------------------------
// Kernel P: per-position work, chip-wide parallel: logits, gumbel-softmax, mm.
// ---------------------------------------------------------------------------
__global__ void __launch_bounds__(256) k_point(const int* __restrict__ amask,
                                               const int* __restrict__ smask,
                                               const float* __restrict__ gum,
                                               const float* __restrict__ bias,
                                               float* __restrict__ out) {
    const int sg = blockIdx.x * 256 + threadIdx.x;           // 0..BB*SS-1
    const int s = sg & (SS - 1);

    float* out_mm     = out + (size_t)BB * SS * HH + (size_t)3 * BB * SS;
    float* out_logits = out_mm + (size_t)BB * SS * 2;

    const float b0v = __ldg(bias + 0), b1v = __ldg(bias + 1);

    float l0, l1;
    if (s < SS - 1) {
        const float4 uvA = *reinterpret_cast<const float4*>(&g_uv[(size_t)sg * 4]);
        const float4 uvB = *reinterpret_cast<const float4*>(&g_uv[(size_t)(sg + 1) * 4]);
        l0 = uvA.x + uvB.z + b0v;
        l1 = uvA.y + uvB.w + b1v;
    } else {                                                 // zero stub row
        l0 = b0v; l1 = b1v;
    }
    out_logits[(size_t)sg * 2 + 0] = l0;
    out_logits[(size_t)sg * 2 + 1] = l1;

    const float z0 = l0 + gum[(size_t)sg * 2 + 0];
    const float z1 = l1 + gum[(size_t)sg * 2 + 1];
    const float m = fmaxf(z0, z1);
    const float e0 = expf(z0 - m), e1 = expf(z1 - m);
    const float inv = 1.f / (e0 + e1);
    const float ys0 = e0 * inv, ys1 = e1 * inv;
    const int idx1 = (ys1 > ys0) ? 1 : 0;                    // argmax, ties -> 0
    float mm0 = ((idx1 == 0 ? 1.f : 0.f) - ys0) + ys0;       // straight-through, exact fp order
    float mm1 = ((idx1 == 1 ? 1.f : 0.f) - ys1) + ys1;
    if (smask[sg]) { mm0 = 1.f; mm1 = 0.f; }
    const float mf = amask[sg] ? 1.f : 0.f;
    mm0 *= mf; mm1 *= mf;
    out_mm[(size_t)sg * 2 + 0] = mm0;
    out_mm[(size_t)sg * 2 + 1] = mm1;
}

// ---------------------------------------------------------------------------
// Kernel B3: per-batch serial part, minimal barriers. Computes T, want, v,
// the prefix scan of inc (warp-0 shuffle scan), segment map, small outputs.
// ---------------------------------------------------------------------------
__global__ void __launch_bounds__(256) k_scan2(const int* __restrict__ amask,
                                               float* __restrict__ out) {
    const int b = blockIdx.x;
    const int tid = threadIdx.x;
    const size_t base = (size_t)b * SS;

    __shared__ unsigned char want_sh[SS];
    __shared__ int r_sh[SS];
    __shared__ int part[256];
    __shared__ int cnt_sh[SS];
    __shared__ int sst_sh[SS];
    __shared__ int sh_T;

    float* out_mask    = out + (size_t)BB * SS * HH;
    float* out_special = out_mask + (size_t)BB * SS;
    float* out_counts  = out_special + (size_t)BB * SS;
    const float* out_mm = out_counts + (size_t)BB * SS;

    // --- T: thread partials + warp-0 reduce (2 barriers) ---
    {
        int local = 0;
#pragma unroll
        for (int i = 0; i < 8; i++) local += amask[base + tid * 8 + i];
        part[tid] = local;
    }
    __syncthreads();
    if (tid < 32) {
        int s = 0;
#pragma unroll
        for (int i = 0; i < 8; i++) s += part[tid * 8 + i];
#pragma unroll
        for (int off = 16; off > 0; off >>= 1) s += __shfl_down_sync(0xffffffffu, s, off);
        if (tid == 0) sh_T = s;
    }
    __syncthreads();
    const int T = sh_T;

    // --- want + v from out_mm (4 float4 loads per thread) ---
#pragma unroll
    for (int q = 0; q < 4; q++) {
        const float4 mm2 = *reinterpret_cast<const float4*>(
            out_mm + (base + tid * 8) * 2 + q * 4);          // positions tid*8+2q, +1
        const int s0 = tid * 8 + q * 2;
        const bool w0 = (mm2.y > 0.5f) && (s0 >= 1) && (s0 < T - 1);
        const bool w1 = (mm2.w > 0.5f) && (s0 + 1 >= 1) && (s0 + 1 < T - 1);
        want_sh[s0]     = w0 ? 1 : 0;
        want_sh[s0 + 1] = w1 ? 1 : 0;
        float v0 = w0 ? mm2.y : mm2.x;
        float v1 = w1 ? mm2.w : mm2.z;
        if (s0 == 0) v0 = 1.f;
        if (s0 >= T) v0 = 0.f;
        if (s0 + 1 >= T) v1 = 0.f;
        g_v[base + s0]     = v0;
        g_v[base + s0 + 1] = v1;
    }
    __syncthreads();

    // --- inc + scan: thread partials, warp-0 shuffle scan (2 barriers) ---
    int incs[8];
    {
        int csum = 0;
#pragma unroll
        for (int i = 0; i < 8; i++) {
            const int s = tid * 8 + i;
            const int w = want_sh[s];
            const int wp = (s > 0) ? want_sh[s - 1] : 0;
            const int inc = (s < T && s >= 1 && !(w && wp)) ? 1 : 0;
            csum += inc;
            incs[i] = csum;                          // local inclusive
        }
        part[tid] = csum;
    }
    __syncthreads();
    if (tid < 32) {
        int vals[8];
        int tot = 0;
#pragma unroll
        for (int i = 0; i < 8; i++) { tot += part[tid * 8 + i]; vals[i] = tot; }
        int sc = tot;
#pragma unroll
        for (int off = 1; off < 32; off <<= 1) {
            const int n = __shfl_up_sync(0xffffffffu, sc, off);
            if (tid >= off) sc += n;
        }
        const int excl = sc - tot;
#pragma unroll
        for (int i = 0; i < 8; i++) part[tid * 8 + i] = excl + vals[i];
    }
    __syncthreads();
    {
        const int offset = (tid > 0) ? part[tid - 1] : 0;
#pragma unroll
        for (int i = 0; i < 8; i++) r_sh[tid * 8 + i] = offset + incs[i];
    }

    // --- segment map via shared atomics ---
#pragma unroll
    for (int i = 0; i < 8; i++) { cnt_sh[tid * 8 + i] = 0; sst_sh[tid * 8 + i] = 0x7fffffff; }
    __syncthreads();
#pragma unroll
    for (int i = 0; i < 8; i++) {
        const int s = tid * 8 + i;
        if (s < T) {
            const int r = r_sh[s];
            atomicAdd(&cnt_sh[r], 1);
            atomicMin(&sst_sh[r], s);
        }
    }
    __syncthreads();

    const int nl = r_sh[SS - 1] + 1;                 // matches reference r[:, -1] + 1
#pragma unroll
    for (int i = 0; i < 8; i++) {
        const int t = tid * 8 + i;
        out_mask[base + t]    = (t < nl) ? 1.f : 0.f;
        out_special[base + t] = (t == 0 || t == nl - 1) ? 1.f : 0.f;
        out_counts[base + t]  = (float)cnt_sh[t];
        g_seg_start[base + t] = sst_sh[t];
        g_seg_len[base + t]   = cnt_sh[t];   // 0 for t >= nl
    }
    if (tid == 0) g_new_len[b] = nl;
}

// ---------------------------------------------------------------------------
// Kernel C v3: 8 output rows per 256-thread block, latency chains broken:
//   (1) seg metadata for all 8 rows via 4x LDG.128, in flight together
//   (2) first-input v for all 8 rows issued together
//   (3) rows processed in independent PAIRS: all 4 h-LDG.128 of a pair issue
//       before any FMA; L>=2 leftovers handled serially (uncommon)
//   (4) nl test gone: seg_len==0 for t>=new_len already yields zeros
// Descending traversal + __stcs stores kept (L2 reuse of k_dots' stream).
// ---------------------------------------------------------------------------
__global__ void __launch_bounds__(256) k_merge(const float* __restrict__ h,
                                               float* __restrict__ out) {
    const int blk = (BB * SS / 8 - 1) - blockIdx.x;  // descending traversal
    const int t0 = blk * 8;                          // first global output row
    const int b = t0 >> 11;                          // batch (8 rows never straddle)
    const int tid = threadIdx.x;
    const int q0 = tid * 2;
    const size_t base = (size_t)b * SS;
    const float4* hb = reinterpret_cast<const float4*>(h);

    // (1) metadata for 8 rows: 4 wide loads, all independent
    const int4 stA = *reinterpret_cast<const int4*>(&g_seg_start[t0]);
    const int4 stB = *reinterpret_cast<const int4*>(&g_seg_start[t0 + 4]);
    const int4 lnA = *reinterpret_cast<const int4*>(&g_seg_len[t0]);
    const int4 lnB = *reinterpret_cast<const int4*>(&g_seg_len[t0 + 4]);
    int st[8] = {stA.x, stA.y, stA.z, stA.w, stB.x, stB.y, stB.z, stB.w};
    const int ln[8] = {lnA.x, lnA.y, lnA.z, lnA.w, lnB.x, lnB.y, lnB.z, lnB.w};

    // (2) sanitize starts and batch the first-input v loads
    float v0[8];
#pragma unroll
    for (int j = 0; j < 8; j++) {
        if (ln[j] == 0) st[j] = 0;                   // safe dummy (weight forced 0)
        v0[j] = (ln[j] > 0) ? __ldg(g_v + base + st[j]) : 0.f;
    }

    // (3) pairs: 4 wide h loads in flight per pair; pairs independent
#pragma unroll
    for (int jp = 0; jp < 4; jp++) {
        const int jA = 2 * jp, jB = 2 * jp + 1;
        const float4* hA = hb + (base + st[jA]) * (HH / 4);
        const float4* hB = hb + (base + st[jB]) * (HH / 4);
        const float4 a0 = __ldg(hA + q0);
        const float4 a1 = __ldg(hA + q0 + 1);
        const float4 b0 = __ldg(hB + q0);
        const float4 b1 = __ldg(hB + q0 + 1);

        const float vA = v0[jA], vB = v0[jB];
        float4 accA0 = make_float4(vA * a0.x, vA * a0.y, vA * a0.z, vA * a0.w);
        float4 accA1 = make_float4(vA * a1.x, vA * a1.y, vA * a1.z, vA * a1.w);
        float4 accB0 = make_float4(vB * b0.x, vB * b0.y, vB * b0.z, vB * b0.w);
        float4 accB1 = make_float4(vB * b1.x, vB * b1.y, vB * b1.z, vB * b1.w);

        for (int i = 1; i < ln[jA]; i++) {           // uncommon leftovers
            const size_t srow = base + st[jA] + i;
            const float w = __ldg(g_v + srow);
            const float4* hr = hb + srow * (HH / 4);
            const float4 x0 = __ldg(hr + q0);
            const float4 x1 = __ldg(hr + q0 + 1);
            accA0.x += w * x0.x; accA0.y += w * x0.y; accA0.z += w * x0.z; accA0.w += w * x0.w;
            accA1.x += w * x1.x; accA1.y += w * x1.y; accA1.z += w * x1.z; accA1.w += w * x1.w;
        }
        for (int i = 1; i < ln[jB]; i++) {
            const size_t srow = base + st[jB] + i;
            const float w = __ldg(g_v + srow);
            const float4* hr = hb + srow * (HH / 4);
            const float4 x0 = __ldg(hr + q0);
            const float4 x1 = __ldg(hr + q0 + 1);
            accB0.x += w * x0.x; accB0.y += w * x0.y; accB0.z += w * x0.z; accB0.w += w * x0.w;
            accB1.x += w * x1.x; accB1.y += w * x1.y; accB1.z += w * x1.z; accB1.w += w * x1.w;
        }

        float4* oA = reinterpret_cast<float4*>(out) + (size_t)(t0 + jA) * (HH / 4);
        float4* oB = reinterpret_cast<float4*>(out) + (size_t)(t0 + jB) * (HH / 4);
        __stcs(oA + q0,     accA0);
        __stcs(oA + q0 + 1, accA1);
        __stcs(oB + q0,     accB0);
        __stcs(oB + q0 + 1, accB1);
    }
}

// ---------------------------------------------------------------------------
extern "C" void kernel_launch(void* const* d_in, const int* in_sizes, int n_in,
                              void* d_out, int out_size) {
    const float* h     = (const float*)d_in[0];   // [B,S,H] f32
    const int*   amask = (const int*)d_in[1];     // [B,S]   i32
    const int*   smask = (const int*)d_in[2];     // [B,S]   i32
    const float* gum   = (const float*)d_in[3];   // [B,S,2] f32
    const float* W     = (const float*)d_in[4];   // [2H,2]  f32
    const float* bias  = (const float*)d_in[5];   // [2]     f32
    float* out = (float*)d_out;

    k_dots<<<(BB * SS) / 4, 512>>>(h, W);
    k_point<<<(BB * SS) / 256, 256>>>(amask, smask, gum, bias, out);
    k_scan2<<<BB, 256>>>(amask, out);
    k_merge<<<(BB * SS) / 8, 256>>>(h, out);
}